// round 1
// baseline (speedup 1.0000x reference)
#include <cuda_runtime.h>
#include <cuda_bf16.h>
#include <math.h>

#define BATCH 4
#define SEQ   2048
#define DM    1024
#define NH    16
#define DK    64
#define MROWS (BATCH * SEQ)   // 8192

// -------- scratch (allocation-free: __device__ globals) --------
__device__ float g_Q[MROWS * DM];
__device__ float g_K[MROWS * DM];
__device__ float g_V[MROWS * DM];
__device__ float g_A[MROWS * DM];

// ================= SGEMM: C[M,N] = A[M,K] @ B[K,N] =================
// BM=128, BN=128, BK=16, 256 threads, 8x8 microtile.
__global__ __launch_bounds__(256, 2)
void sgemm128(const float* __restrict__ A, const float* __restrict__ B,
              float* __restrict__ C, int M, int N, int K) {
    __shared__ float As[16][128];
    __shared__ float Bs[16][128];

    const int tid = threadIdx.x;
    const int tx = tid & 15;        // 0..15 -> col microtile
    const int ty = tid >> 4;        // 0..15 -> row microtile
    const int rowC = blockIdx.y * 128;
    const int colC = blockIdx.x * 128;

    // A tile loader: 128x16 floats = 512 float4, 2 per thread
    const int arow  = tid >> 2;     // 0..63
    const int acol4 = tid & 3;      // 0..3 (float4 index along K)
    // B tile loader: 16x128 floats = 512 float4, 2 per thread
    const int brow  = tid >> 5;     // 0..7
    const int bcol4 = tid & 31;     // 0..31

    float acc[8][8];
#pragma unroll
    for (int i = 0; i < 8; i++)
#pragma unroll
        for (int j = 0; j < 8; j++) acc[i][j] = 0.f;

    for (int k0 = 0; k0 < K; k0 += 16) {
#pragma unroll
        for (int r = 0; r < 2; r++) {
            int row = arow + r * 64;
            float4 a = *(const float4*)(A + (size_t)(rowC + row) * K + k0 + acol4 * 4);
            As[acol4 * 4 + 0][row] = a.x;
            As[acol4 * 4 + 1][row] = a.y;
            As[acol4 * 4 + 2][row] = a.z;
            As[acol4 * 4 + 3][row] = a.w;
        }
#pragma unroll
        for (int r = 0; r < 2; r++) {
            int row = brow + r * 8;
            float4 b = *(const float4*)(B + (size_t)(k0 + row) * N + colC + bcol4 * 4);
            *(float4*)&Bs[row][bcol4 * 4] = b;
        }
        __syncthreads();

#pragma unroll
        for (int kk = 0; kk < 16; kk++) {
            float ra[8], rb[8];
            *(float4*)&ra[0] = *(float4*)&As[kk][ty * 8];
            *(float4*)&ra[4] = *(float4*)&As[kk][ty * 8 + 4];
            *(float4*)&rb[0] = *(float4*)&Bs[kk][tx * 8];
            *(float4*)&rb[4] = *(float4*)&Bs[kk][tx * 8 + 4];
#pragma unroll
            for (int i = 0; i < 8; i++)
#pragma unroll
                for (int j = 0; j < 8; j++)
                    acc[i][j] = fmaf(ra[i], rb[j], acc[i][j]);
        }
        __syncthreads();
    }

#pragma unroll
    for (int i = 0; i < 8; i++) {
        float* cp = C + (size_t)(rowC + ty * 8 + i) * N + colC + tx * 8;
        float4 c0 = make_float4(acc[i][0], acc[i][1], acc[i][2], acc[i][3]);
        float4 c1 = make_float4(acc[i][4], acc[i][5], acc[i][6], acc[i][7]);
        *(float4*)(cp)     = c0;
        *(float4*)(cp + 4) = c1;
    }
}

// ================= Flash attention (causal) =================
// grid: (SEQ/64, BATCH*NH). 256 threads (16x16), each owns a 4x4 patch of the
// 64x64 score tile. Online softmax. P tile reuses the K smem buffer.
#define ATTN_SMEM_FLOATS (64 * 64 + 64 * 65 + 64 * 64)
#define ATTN_SMEM_BYTES  (ATTN_SMEM_FLOATS * 4)

__global__ __launch_bounds__(256, 1)
void attn_kernel(const float* __restrict__ Qg, const float* __restrict__ Kg,
                 const float* __restrict__ Vg, float* __restrict__ Og) {
    extern __shared__ float sm[];
    float* Qs = sm;                 // [64][64]
    float* Ks = sm + 4096;          // [64][65]  (also reused as P tile)
    float* Vs = sm + 4096 + 4160;   // [64][64]

    const int bh = blockIdx.y;
    const int b  = bh >> 4;
    const int h  = bh & 15;
    const int m0 = blockIdx.x * 64;

    const size_t base = (size_t)b * SEQ * DM + (size_t)h * DK;
    const float* Qb = Qg + base;
    const float* Kb = Kg + base;
    const float* Vb = Vg + base;
    float*       Ob = Og + base;

    const int tid = threadIdx.x;
    const int tx = tid & 15;
    const int ty = tid >> 4;
    const int r0 = ty * 4;   // rows of this thread's patch (within tile)
    const int c0 = tx * 4;   // cols of this thread's patch

    // load Q tile (scaled by 1/sqrt(dk) = 0.125)
    for (int rr = ty; rr < 64; rr += 16) {
        float4 q = *(const float4*)(Qb + (size_t)(m0 + rr) * DM + tx * 4);
        Qs[rr * 64 + tx * 4 + 0] = q.x * 0.125f;
        Qs[rr * 64 + tx * 4 + 1] = q.y * 0.125f;
        Qs[rr * 64 + tx * 4 + 2] = q.z * 0.125f;
        Qs[rr * 64 + tx * 4 + 3] = q.w * 0.125f;
    }

    float m_i[4], l_i[4], o[4][4];
#pragma unroll
    for (int i = 0; i < 4; i++) {
        m_i[i] = -INFINITY; l_i[i] = 0.f;
#pragma unroll
        for (int j = 0; j < 4; j++) o[i][j] = 0.f;
    }

    for (int n0 = 0; n0 <= m0; n0 += 64) {
        // load K (padded, row = key) and V tiles
        for (int rr = ty; rr < 64; rr += 16) {
            float4 k = *(const float4*)(Kb + (size_t)(n0 + rr) * DM + tx * 4);
            Ks[rr * 65 + tx * 4 + 0] = k.x;
            Ks[rr * 65 + tx * 4 + 1] = k.y;
            Ks[rr * 65 + tx * 4 + 2] = k.z;
            Ks[rr * 65 + tx * 4 + 3] = k.w;
            float4 v = *(const float4*)(Vb + (size_t)(n0 + rr) * DM + tx * 4);
            *(float4*)&Vs[rr * 64 + tx * 4] = v;
        }
        __syncthreads();

        // scores S = Q K^T (4x4 patch)
        float s[4][4];
#pragma unroll
        for (int i = 0; i < 4; i++)
#pragma unroll
            for (int j = 0; j < 4; j++) s[i][j] = 0.f;

        for (int kk = 0; kk < 64; kk++) {
            float qv[4], kv[4];
#pragma unroll
            for (int i = 0; i < 4; i++) qv[i] = Qs[(r0 + i) * 64 + kk];
#pragma unroll
            for (int j = 0; j < 4; j++) kv[j] = Ks[(c0 + j) * 65 + kk];
#pragma unroll
            for (int i = 0; i < 4; i++)
#pragma unroll
                for (int j = 0; j < 4; j++)
                    s[i][j] = fmaf(qv[i], kv[j], s[i][j]);
        }

        // causal mask: only the diagonal tile needs it (n0 == m0)
        if (n0 == m0) {
#pragma unroll
            for (int i = 0; i < 4; i++)
#pragma unroll
                for (int j = 0; j < 4; j++)
                    if (c0 + j > r0 + i) s[i][j] = -INFINITY;
        }

        // online softmax update
        float mnew[4], lsum[4];
#pragma unroll
        for (int i = 0; i < 4; i++) {
            float mx = fmaxf(fmaxf(s[i][0], s[i][1]), fmaxf(s[i][2], s[i][3]));
#pragma unroll
            for (int w = 1; w < 16; w <<= 1)
                mx = fmaxf(mx, __shfl_xor_sync(0xffffffffu, mx, w, 16));
            mnew[i] = fmaxf(m_i[i], mx);
            float sum = 0.f;
#pragma unroll
            for (int j = 0; j < 4; j++) {
                s[i][j] = __expf(s[i][j] - mnew[i]);
                sum += s[i][j];
            }
#pragma unroll
            for (int w = 1; w < 16; w <<= 1)
                sum += __shfl_xor_sync(0xffffffffu, sum, w, 16);
            lsum[i] = sum;
        }
#pragma unroll
        for (int i = 0; i < 4; i++) {
            float alpha = __expf(m_i[i] - mnew[i]);
            l_i[i] = l_i[i] * alpha + lsum[i];
            m_i[i] = mnew[i];
#pragma unroll
            for (int j = 0; j < 4; j++) o[i][j] *= alpha;
        }

        __syncthreads();   // everyone done reading Ks before P overwrites it
        // store P into Ks buffer
#pragma unroll
        for (int i = 0; i < 4; i++)
#pragma unroll
            for (int j = 0; j < 4; j++)
                Ks[(r0 + i) * 65 + c0 + j] = s[i][j];
        __syncthreads();

        // O += P @ V   (thread owns rows r0..r0+3, dims c0..c0+3)
        for (int c = 0; c < 64; c++) {
            float p0 = Ks[(r0 + 0) * 65 + c];
            float p1 = Ks[(r0 + 1) * 65 + c];
            float p2 = Ks[(r0 + 2) * 65 + c];
            float p3 = Ks[(r0 + 3) * 65 + c];
            float4 v = *(float4*)&Vs[c * 64 + c0];
            o[0][0] = fmaf(p0, v.x, o[0][0]); o[0][1] = fmaf(p0, v.y, o[0][1]);
            o[0][2] = fmaf(p0, v.z, o[0][2]); o[0][3] = fmaf(p0, v.w, o[0][3]);
            o[1][0] = fmaf(p1, v.x, o[1][0]); o[1][1] = fmaf(p1, v.y, o[1][1]);
            o[1][2] = fmaf(p1, v.z, o[1][2]); o[1][3] = fmaf(p1, v.w, o[1][3]);
            o[2][0] = fmaf(p2, v.x, o[2][0]); o[2][1] = fmaf(p2, v.y, o[2][1]);
            o[2][2] = fmaf(p2, v.z, o[2][2]); o[2][3] = fmaf(p2, v.w, o[2][3]);
            o[3][0] = fmaf(p3, v.x, o[3][0]); o[3][1] = fmaf(p3, v.y, o[3][1]);
            o[3][2] = fmaf(p3, v.z, o[3][2]); o[3][3] = fmaf(p3, v.w, o[3][3]);
        }
        __syncthreads();   // before next tile's K/V loads overwrite smem
    }

    // finalize + store (layout already == [b, s, h*dk + d])
#pragma unroll
    for (int i = 0; i < 4; i++) {
        float inv = 1.f / l_i[i];
        float4 out = make_float4(o[i][0] * inv, o[i][1] * inv,
                                 o[i][2] * inv, o[i][3] * inv);
        *(float4*)(Ob + (size_t)(m0 + r0 + i) * DM + c0) = out;
    }
}

// ================= launch =================
extern "C" void kernel_launch(void* const* d_in, const int* in_sizes, int n_in,
                              void* d_out, int out_size) {
    (void)in_sizes; (void)n_in; (void)out_size;
    const float* X  = (const float*)d_in[0];
    const float* Wq = (const float*)d_in[1];
    const float* Wk = (const float*)d_in[2];
    const float* Wv = (const float*)d_in[3];
    const float* Wo = (const float*)d_in[4];

    float *q, *k, *v, *a;
    cudaGetSymbolAddress((void**)&q, g_Q);
    cudaGetSymbolAddress((void**)&k, g_K);
    cudaGetSymbolAddress((void**)&v, g_V);
    cudaGetSymbolAddress((void**)&a, g_A);

    cudaFuncSetAttribute(attn_kernel,
                         cudaFuncAttributeMaxDynamicSharedMemorySize,
                         ATTN_SMEM_BYTES);

    dim3 gGemm(DM / 128, MROWS / 128);   // (8, 64)
    dim3 blk(256);

    sgemm128<<<gGemm, blk>>>(X, Wq, q, MROWS, DM, DM);
    sgemm128<<<gGemm, blk>>>(X, Wk, k, MROWS, DM, DM);
    sgemm128<<<gGemm, blk>>>(X, Wv, v, MROWS, DM, DM);

    dim3 gAttn(SEQ / 64, BATCH * NH);    // (32, 64)
    attn_kernel<<<gAttn, blk, ATTN_SMEM_BYTES>>>(q, k, v, a);

    sgemm128<<<gGemm, blk>>>(a, Wo, (float*)d_out, MROWS, DM, DM);
}

// round 3
// speedup vs baseline: 1.5784x; 1.5784x over previous
#include <cuda_runtime.h>
#include <cuda_bf16.h>
#include <cstdint>
#include <math.h>

#define BATCH 4
#define SEQ   2048
#define DM    1024
#define NH    16
#define DK    64
#define MROWS (BATCH * SEQ)   // 8192

// ---------------- scratch (allocation-free: __device__ globals) ----------------
__device__ float g_Q[MROWS * DM];
__device__ float g_K[MROWS * DM];
__device__ float g_V[MROWS * DM];
__device__ float g_A[MROWS * DM];

__device__ __nv_bfloat16 g_Xhi[MROWS * DM];
__device__ __nv_bfloat16 g_Xlo[MROWS * DM];
__device__ __nv_bfloat16 g_Ahi[MROWS * DM];
__device__ __nv_bfloat16 g_Alo[MROWS * DM];

__device__ __nv_bfloat16 g_Wqh[DM * DM], g_Wql[DM * DM];
__device__ __nv_bfloat16 g_Wkh[DM * DM], g_Wkl[DM * DM];
__device__ __nv_bfloat16 g_Wvh[DM * DM], g_Wvl[DM * DM];
__device__ __nv_bfloat16 g_Woh[DM * DM], g_Wol[DM * DM];

// ---------------- conversion kernels ----------------
__global__ void convert_hilo(const float4* __restrict__ x,
                             uint2* __restrict__ hi, uint2* __restrict__ lo, int n4) {
    int i = blockIdx.x * 256 + threadIdx.x;
    if (i >= n4) return;
    float4 v = x[i];
    __nv_bfloat16 h0 = __float2bfloat16(v.x), h1 = __float2bfloat16(v.y);
    __nv_bfloat16 h2 = __float2bfloat16(v.z), h3 = __float2bfloat16(v.w);
    __nv_bfloat16 l0 = __float2bfloat16(v.x - __bfloat162float(h0));
    __nv_bfloat16 l1 = __float2bfloat16(v.y - __bfloat162float(h1));
    __nv_bfloat16 l2 = __float2bfloat16(v.z - __bfloat162float(h2));
    __nv_bfloat16 l3 = __float2bfloat16(v.w - __bfloat162float(h3));
    union U { __nv_bfloat16 b[4]; uint2 u; } uh, ul;
    uh.b[0] = h0; uh.b[1] = h1; uh.b[2] = h2; uh.b[3] = h3;
    ul.b[0] = l0; ul.b[1] = l1; ul.b[2] = l2; ul.b[3] = l3;
    hi[i] = uh.u;
    lo[i] = ul.u;
}

// W[K][N] fp32 -> Wt[N][K] bf16 hi/lo (transpose + split)
__global__ void wtrans_hilo(const float* __restrict__ W,
                            __nv_bfloat16* __restrict__ Th,
                            __nv_bfloat16* __restrict__ Tl) {
    __shared__ float t[32][33];
    int tx = threadIdx.x, ty = threadIdx.y;
    int col  = blockIdx.x * 32 + tx;   // n
    int row0 = blockIdx.y * 32;        // k
    for (int j = ty; j < 32; j += 8)
        t[j][tx] = W[(size_t)(row0 + j) * DM + col];
    __syncthreads();
    int ocol  = row0 + tx;             // k (contiguous out)
    int orow0 = blockIdx.x * 32;       // n
    for (int j = ty; j < 32; j += 8) {
        float v = t[tx][j];
        __nv_bfloat16 h = __float2bfloat16(v);
        __nv_bfloat16 l = __float2bfloat16(v - __bfloat162float(h));
        Th[(size_t)(orow0 + j) * DM + ocol] = h;
        Tl[(size_t)(orow0 + j) * DM + ocol] = l;
    }
}

// ---------------- HMMA bf16x3 GEMM ----------------
// C[M,N] = A[M,K] @ Bt[N,K]^T ; A,B as bf16 hi/lo. mma.sync m16n8k16 (sm_80+ path).
// 128x128 tile/CTA, BK=32, 8 warps (2m x 4n), each 64x32. cp.async double buffer.

#define GBK 32
#define MAT_ELEMS (128 * GBK)                 // 4096 bf16 = 8KB
#define STAGE_ELEMS (4 * MAT_ELEMS)           // Ah, Al, Bh, Bl
#define GEMM_SMEM_BYTES (2 * STAGE_ELEMS * 2) // 64KB

__device__ __forceinline__ uint32_t smem_u32(const void* p) {
    uint32_t a;
    asm("{ .reg .u64 t; cvta.to.shared.u64 t, %1; cvt.u32.u64 %0, t; }"
        : "=r"(a) : "l"(p));
    return a;
}
#define CP_ASYNC16(dst, src) \
    asm volatile("cp.async.cg.shared.global [%0], [%1], 16;" :: "r"(dst), "l"(src))
#define CP_COMMIT() asm volatile("cp.async.commit_group;" ::: "memory")
#define CP_WAIT(n)  asm volatile("cp.async.wait_group %0;" :: "n"(n) : "memory")

// swizzled element offset within one [128][GBK] bf16 matrix (16B-quad XOR)
__device__ __forceinline__ int swz(int row, int k) {
    int quad = (k >> 3) ^ (row & 3) ^ ((row >> 2) & 1);
    return row * GBK + quad * 8 + (k & 7);
}

__device__ __forceinline__ void mma_bf16(float* d, uint32_t a0, uint32_t a1,
                                         uint32_t a2, uint32_t a3,
                                         uint32_t b0, uint32_t b1) {
    asm volatile(
        "mma.sync.aligned.m16n8k16.row.col.f32.bf16.bf16.f32 "
        "{%0,%1,%2,%3}, {%4,%5,%6,%7}, {%8,%9}, {%0,%1,%2,%3};"
        : "+f"(d[0]), "+f"(d[1]), "+f"(d[2]), "+f"(d[3])
        : "r"(a0), "r"(a1), "r"(a2), "r"(a3), "r"(b0), "r"(b1));
}

__global__ __launch_bounds__(256, 2)
void gemm_bf16x3(const __nv_bfloat16* __restrict__ Ahi,
                 const __nv_bfloat16* __restrict__ Alo,
                 const __nv_bfloat16* __restrict__ Bhi,
                 const __nv_bfloat16* __restrict__ Blo,
                 float* __restrict__ C, int M, int N, int K) {
    extern __shared__ __nv_bfloat16 sm[];
    const int tid = threadIdx.x;
    const int wid = tid >> 5;
    const int lane = tid & 31;
    const int rowC = blockIdx.y * 128;
    const int colC = blockIdx.x * 128;

    const int wm = (wid >> 2) * 64;   // warp m offset (0 or 64)
    const int wn = (wid & 3) * 32;    // warp n offset
    const int r  = lane >> 2;         // 0..7
    const int cq = (lane & 3) * 2;    // 0,2,4,6

    float acc[4][4][4];
#pragma unroll
    for (int i = 0; i < 4; i++)
#pragma unroll
        for (int j = 0; j < 4; j++)
#pragma unroll
            for (int t = 0; t < 4; t++) acc[i][j][t] = 0.f;

    const uint32_t smb = smem_u32(sm);

    // loader lambda: stage s, k-chunk c. 2048 16B transfers, 8 per thread.
    auto load_stage = [&](int s, int c) {
        const size_t k0 = (size_t)c * GBK;
        __nv_bfloat16* st = sm + s * STAGE_ELEMS;
#pragma unroll
        for (int t = 0; t < 2; t++) {
            int idx = tid + t * 256;        // 0..511
            int row = idx >> 2;             // 0..127
            int q   = idx & 3;              // quad along k
            uint32_t dsto = smem_u32(st) + swz(row, q * 8) * 2;
            const __nv_bfloat16* ga = Ahi + (size_t)(rowC + row) * K + k0 + q * 8;
            const __nv_bfloat16* gl = Alo + (size_t)(rowC + row) * K + k0 + q * 8;
            const __nv_bfloat16* gb = Bhi + (size_t)(colC + row) * K + k0 + q * 8;
            const __nv_bfloat16* gc = Blo + (size_t)(colC + row) * K + k0 + q * 8;
            CP_ASYNC16(dsto,                     ga);
            CP_ASYNC16(dsto + MAT_ELEMS * 2,     gl);
            CP_ASYNC16(dsto + MAT_ELEMS * 4,     gb);
            CP_ASYNC16(dsto + MAT_ELEMS * 6,     gc);
        }
    };

    const int nchunk = K / GBK;
    load_stage(0, 0);
    CP_COMMIT();

    for (int c = 0; c < nchunk; c++) {
        const int s = c & 1;
        if (c + 1 < nchunk) {
            load_stage(s ^ 1, c + 1);
            CP_COMMIT();
            CP_WAIT(1);
        } else {
            CP_WAIT(0);
        }
        __syncthreads();

        const __nv_bfloat16* Ah_s = sm + s * STAGE_ELEMS;
        const __nv_bfloat16* Al_s = Ah_s + MAT_ELEMS;
        const __nv_bfloat16* Bh_s = Ah_s + 2 * MAT_ELEMS;
        const __nv_bfloat16* Bl_s = Ah_s + 3 * MAT_ELEMS;

#pragma unroll
        for (int kk = 0; kk < GBK; kk += 16) {
            uint32_t ra[4][4], rb[4][2];
            // ---- term 1: Ah x Bh ----
#pragma unroll
            for (int i = 0; i < 4; i++) {
                int m = wm + i * 16;
                ra[i][0] = *(const uint32_t*)(Ah_s + swz(m + r,     kk + cq));
                ra[i][1] = *(const uint32_t*)(Ah_s + swz(m + r + 8, kk + cq));
                ra[i][2] = *(const uint32_t*)(Ah_s + swz(m + r,     kk + cq + 8));
                ra[i][3] = *(const uint32_t*)(Ah_s + swz(m + r + 8, kk + cq + 8));
            }
#pragma unroll
            for (int j = 0; j < 4; j++) {
                int n = wn + j * 8 + r;
                rb[j][0] = *(const uint32_t*)(Bh_s + swz(n, kk + cq));
                rb[j][1] = *(const uint32_t*)(Bh_s + swz(n, kk + cq + 8));
            }
#pragma unroll
            for (int i = 0; i < 4; i++)
#pragma unroll
                for (int j = 0; j < 4; j++)
                    mma_bf16(acc[i][j], ra[i][0], ra[i][1], ra[i][2], ra[i][3],
                             rb[j][0], rb[j][1]);
            // ---- term 2: Ah x Bl (reuse ra) ----
#pragma unroll
            for (int j = 0; j < 4; j++) {
                int n = wn + j * 8 + r;
                rb[j][0] = *(const uint32_t*)(Bl_s + swz(n, kk + cq));
                rb[j][1] = *(const uint32_t*)(Bl_s + swz(n, kk + cq + 8));
            }
#pragma unroll
            for (int i = 0; i < 4; i++)
#pragma unroll
                for (int j = 0; j < 4; j++)
                    mma_bf16(acc[i][j], ra[i][0], ra[i][1], ra[i][2], ra[i][3],
                             rb[j][0], rb[j][1]);
            // ---- term 3: Al x Bh ----
#pragma unroll
            for (int i = 0; i < 4; i++) {
                int m = wm + i * 16;
                ra[i][0] = *(const uint32_t*)(Al_s + swz(m + r,     kk + cq));
                ra[i][1] = *(const uint32_t*)(Al_s + swz(m + r + 8, kk + cq));
                ra[i][2] = *(const uint32_t*)(Al_s + swz(m + r,     kk + cq + 8));
                ra[i][3] = *(const uint32_t*)(Al_s + swz(m + r + 8, kk + cq + 8));
            }
#pragma unroll
            for (int j = 0; j < 4; j++) {
                int n = wn + j * 8 + r;
                rb[j][0] = *(const uint32_t*)(Bh_s + swz(n, kk + cq));
                rb[j][1] = *(const uint32_t*)(Bh_s + swz(n, kk + cq + 8));
            }
#pragma unroll
            for (int i = 0; i < 4; i++)
#pragma unroll
                for (int j = 0; j < 4; j++)
                    mma_bf16(acc[i][j], ra[i][0], ra[i][1], ra[i][2], ra[i][3],
                             rb[j][0], rb[j][1]);
        }
        __syncthreads();
    }
    (void)smb;

    // epilogue
#pragma unroll
    for (int i = 0; i < 4; i++) {
        int row0 = rowC + wm + i * 16 + r;
#pragma unroll
        for (int j = 0; j < 4; j++) {
            int col = colC + wn + j * 8 + cq;
            *(float2*)(C + (size_t)row0 * N + col) =
                make_float2(acc[i][j][0], acc[i][j][1]);
            *(float2*)(C + (size_t)(row0 + 8) * N + col) =
                make_float2(acc[i][j][2], acc[i][j][3]);
        }
    }
}

// ================= Flash attention (causal) — unchanged =================
#define ATTN_SMEM_FLOATS (64 * 64 + 64 * 65 + 64 * 64)
#define ATTN_SMEM_BYTES  (ATTN_SMEM_FLOATS * 4)

__global__ __launch_bounds__(256, 1)
void attn_kernel(const float* __restrict__ Qg, const float* __restrict__ Kg,
                 const float* __restrict__ Vg, float* __restrict__ Og) {
    extern __shared__ float smf[];
    float* Qs = smf;
    float* Ks = smf + 4096;
    float* Vs = smf + 4096 + 4160;

    const int bh = blockIdx.y;
    const int b  = bh >> 4;
    const int h  = bh & 15;
    const int m0 = blockIdx.x * 64;

    const size_t base = (size_t)b * SEQ * DM + (size_t)h * DK;
    const float* Qb = Qg + base;
    const float* Kb = Kg + base;
    const float* Vb = Vg + base;
    float*       Ob = Og + base;

    const int tid = threadIdx.x;
    const int tx = tid & 15;
    const int ty = tid >> 4;
    const int r0 = ty * 4;
    const int c0 = tx * 4;

    for (int rr = ty; rr < 64; rr += 16) {
        float4 q = *(const float4*)(Qb + (size_t)(m0 + rr) * DM + tx * 4);
        Qs[rr * 64 + tx * 4 + 0] = q.x * 0.125f;
        Qs[rr * 64 + tx * 4 + 1] = q.y * 0.125f;
        Qs[rr * 64 + tx * 4 + 2] = q.z * 0.125f;
        Qs[rr * 64 + tx * 4 + 3] = q.w * 0.125f;
    }

    float m_i[4], l_i[4], o[4][4];
#pragma unroll
    for (int i = 0; i < 4; i++) {
        m_i[i] = -INFINITY; l_i[i] = 0.f;
#pragma unroll
        for (int j = 0; j < 4; j++) o[i][j] = 0.f;
    }

    for (int n0 = 0; n0 <= m0; n0 += 64) {
        for (int rr = ty; rr < 64; rr += 16) {
            float4 k = *(const float4*)(Kb + (size_t)(n0 + rr) * DM + tx * 4);
            Ks[rr * 65 + tx * 4 + 0] = k.x;
            Ks[rr * 65 + tx * 4 + 1] = k.y;
            Ks[rr * 65 + tx * 4 + 2] = k.z;
            Ks[rr * 65 + tx * 4 + 3] = k.w;
            float4 v = *(const float4*)(Vb + (size_t)(n0 + rr) * DM + tx * 4);
            *(float4*)&Vs[rr * 64 + tx * 4] = v;
        }
        __syncthreads();

        float s[4][4];
#pragma unroll
        for (int i = 0; i < 4; i++)
#pragma unroll
            for (int j = 0; j < 4; j++) s[i][j] = 0.f;

        for (int kk = 0; kk < 64; kk++) {
            float qv[4], kv[4];
#pragma unroll
            for (int i = 0; i < 4; i++) qv[i] = Qs[(r0 + i) * 64 + kk];
#pragma unroll
            for (int j = 0; j < 4; j++) kv[j] = Ks[(c0 + j) * 65 + kk];
#pragma unroll
            for (int i = 0; i < 4; i++)
#pragma unroll
                for (int j = 0; j < 4; j++)
                    s[i][j] = fmaf(qv[i], kv[j], s[i][j]);
        }

        if (n0 == m0) {
#pragma unroll
            for (int i = 0; i < 4; i++)
#pragma unroll
                for (int j = 0; j < 4; j++)
                    if (c0 + j > r0 + i) s[i][j] = -INFINITY;
        }

        float mnew[4], lsum[4];
#pragma unroll
        for (int i = 0; i < 4; i++) {
            float mx = fmaxf(fmaxf(s[i][0], s[i][1]), fmaxf(s[i][2], s[i][3]));
#pragma unroll
            for (int w = 1; w < 16; w <<= 1)
                mx = fmaxf(mx, __shfl_xor_sync(0xffffffffu, mx, w, 16));
            mnew[i] = fmaxf(m_i[i], mx);
            float sum = 0.f;
#pragma unroll
            for (int j = 0; j < 4; j++) {
                s[i][j] = __expf(s[i][j] - mnew[i]);
                sum += s[i][j];
            }
#pragma unroll
            for (int w = 1; w < 16; w <<= 1)
                sum += __shfl_xor_sync(0xffffffffu, sum, w, 16);
            lsum[i] = sum;
        }
#pragma unroll
        for (int i = 0; i < 4; i++) {
            float alpha = __expf(m_i[i] - mnew[i]);
            l_i[i] = l_i[i] * alpha + lsum[i];
            m_i[i] = mnew[i];
#pragma unroll
            for (int j = 0; j < 4; j++) o[i][j] *= alpha;
        }

        __syncthreads();
#pragma unroll
        for (int i = 0; i < 4; i++)
#pragma unroll
            for (int j = 0; j < 4; j++)
                Ks[(r0 + i) * 65 + c0 + j] = s[i][j];
        __syncthreads();

        for (int c = 0; c < 64; c++) {
            float p0 = Ks[(r0 + 0) * 65 + c];
            float p1 = Ks[(r0 + 1) * 65 + c];
            float p2 = Ks[(r0 + 2) * 65 + c];
            float p3 = Ks[(r0 + 3) * 65 + c];
            float4 v = *(float4*)&Vs[c * 64 + c0];
            o[0][0] = fmaf(p0, v.x, o[0][0]); o[0][1] = fmaf(p0, v.y, o[0][1]);
            o[0][2] = fmaf(p0, v.z, o[0][2]); o[0][3] = fmaf(p0, v.w, o[0][3]);
            o[1][0] = fmaf(p1, v.x, o[1][0]); o[1][1] = fmaf(p1, v.y, o[1][1]);
            o[1][2] = fmaf(p1, v.z, o[1][2]); o[1][3] = fmaf(p1, v.w, o[1][3]);
            o[2][0] = fmaf(p2, v.x, o[2][0]); o[2][1] = fmaf(p2, v.y, o[2][1]);
            o[2][2] = fmaf(p2, v.z, o[2][2]); o[2][3] = fmaf(p2, v.w, o[2][3]);
            o[3][0] = fmaf(p3, v.x, o[3][0]); o[3][1] = fmaf(p3, v.y, o[3][1]);
            o[3][2] = fmaf(p3, v.z, o[3][2]); o[3][3] = fmaf(p3, v.w, o[3][3]);
        }
        __syncthreads();
    }

#pragma unroll
    for (int i = 0; i < 4; i++) {
        float inv = 1.f / l_i[i];
        float4 out = make_float4(o[i][0] * inv, o[i][1] * inv,
                                 o[i][2] * inv, o[i][3] * inv);
        *(float4*)(Ob + (size_t)(m0 + r0 + i) * DM + c0) = out;
    }
}

// ================= launch =================
extern "C" void kernel_launch(void* const* d_in, const int* in_sizes, int n_in,
                              void* d_out, int out_size) {
    (void)in_sizes; (void)n_in; (void)out_size;
    const float* X  = (const float*)d_in[0];
    const float* Wq = (const float*)d_in[1];
    const float* Wk = (const float*)d_in[2];
    const float* Wv = (const float*)d_in[3];
    const float* Wo = (const float*)d_in[4];

    float *q, *k, *v, *a;
    cudaGetSymbolAddress((void**)&q, g_Q);
    cudaGetSymbolAddress((void**)&k, g_K);
    cudaGetSymbolAddress((void**)&v, g_V);
    cudaGetSymbolAddress((void**)&a, g_A);

    __nv_bfloat16 *xhi, *xlo, *ahi, *alo;
    cudaGetSymbolAddress((void**)&xhi, g_Xhi);
    cudaGetSymbolAddress((void**)&xlo, g_Xlo);
    cudaGetSymbolAddress((void**)&ahi, g_Ahi);
    cudaGetSymbolAddress((void**)&alo, g_Alo);

    __nv_bfloat16 *wqh, *wql, *wkh, *wkl, *wvh, *wvl, *woh, *wol;
    cudaGetSymbolAddress((void**)&wqh, g_Wqh); cudaGetSymbolAddress((void**)&wql, g_Wql);
    cudaGetSymbolAddress((void**)&wkh, g_Wkh); cudaGetSymbolAddress((void**)&wkl, g_Wkl);
    cudaGetSymbolAddress((void**)&wvh, g_Wvh); cudaGetSymbolAddress((void**)&wvl, g_Wvl);
    cudaGetSymbolAddress((void**)&woh, g_Woh); cudaGetSymbolAddress((void**)&wol, g_Wol);

    cudaFuncSetAttribute(attn_kernel,
                         cudaFuncAttributeMaxDynamicSharedMemorySize,
                         ATTN_SMEM_BYTES);
    cudaFuncSetAttribute(gemm_bf16x3,
                         cudaFuncAttributeMaxDynamicSharedMemorySize,
                         GEMM_SMEM_BYTES);

    // 1) split X into bf16 hi/lo
    {
        int n4 = MROWS * DM / 4;
        convert_hilo<<<(n4 + 255) / 256, 256>>>((const float4*)X, (uint2*)xhi, (uint2*)xlo, n4);
    }
    // 2) transpose + split weights
    {
        dim3 g(DM / 32, DM / 32), b(32, 8);
        wtrans_hilo<<<g, b>>>(Wq, wqh, wql);
        wtrans_hilo<<<g, b>>>(Wk, wkh, wkl);
        wtrans_hilo<<<g, b>>>(Wv, wvh, wvl);
        wtrans_hilo<<<g, b>>>(Wo, woh, wol);
    }
    // 3) projection GEMMs on tensor cores (mma.sync path)
    dim3 gGemm(DM / 128, MROWS / 128);   // (8, 64)
    gemm_bf16x3<<<gGemm, 256, GEMM_SMEM_BYTES>>>(xhi, xlo, wqh, wql, q, MROWS, DM, DM);
    gemm_bf16x3<<<gGemm, 256, GEMM_SMEM_BYTES>>>(xhi, xlo, wkh, wkl, k, MROWS, DM, DM);
    gemm_bf16x3<<<gGemm, 256, GEMM_SMEM_BYTES>>>(xhi, xlo, wvh, wvl, v, MROWS, DM, DM);

    // 4) attention
    dim3 gAttn(SEQ / 64, BATCH * NH);    // (32, 64)
    attn_kernel<<<gAttn, 256, ATTN_SMEM_BYTES>>>(q, k, v, a);

    // 5) output projection
    {
        int n4 = MROWS * DM / 4;
        convert_hilo<<<(n4 + 255) / 256, 256>>>((const float4*)a, (uint2*)ahi, (uint2*)alo, n4);
    }
    gemm_bf16x3<<<gGemm, 256, GEMM_SMEM_BYTES>>>(ahi, alo, woh, wol, (float*)d_out, MROWS, DM, DM);
}

// round 4
// speedup vs baseline: 3.0163x; 1.9110x over previous
#include <cuda_runtime.h>
#include <cuda_bf16.h>
#include <cstdint>
#include <math.h>

#define BATCH 4
#define SEQ   2048
#define DM    1024
#define NH    16
#define DK    64
#define MROWS (BATCH * SEQ)   // 8192

typedef __nv_bfloat16 bf16;

// ---------------- scratch (allocation-free: __device__ globals) ----------------
__device__ bf16 g_Xhi[MROWS * DM], g_Xlo[MROWS * DM];
__device__ bf16 g_Qh[MROWS * DM], g_Ql[MROWS * DM];
__device__ bf16 g_Kh[MROWS * DM], g_Kl[MROWS * DM];
__device__ bf16 g_Vh[MROWS * DM], g_Vl[MROWS * DM];
__device__ bf16 g_Ahi[MROWS * DM], g_Alo[MROWS * DM];

__device__ bf16 g_Wqh[DM * DM], g_Wql[DM * DM];
__device__ bf16 g_Wkh[DM * DM], g_Wkl[DM * DM];
__device__ bf16 g_Wvh[DM * DM], g_Wvl[DM * DM];
__device__ bf16 g_Woh[DM * DM], g_Wol[DM * DM];

// ---------------- common helpers ----------------
__device__ __forceinline__ uint32_t smem_u32(const void* p) {
    uint32_t a;
    asm("{ .reg .u64 t; cvta.to.shared.u64 t, %1; cvt.u32.u64 %0, t; }"
        : "=r"(a) : "l"(p));
    return a;
}
#define CP_ASYNC16(dst, src) \
    asm volatile("cp.async.cg.shared.global [%0], [%1], 16;" :: "r"(dst), "l"(src))
#define CP_COMMIT() asm volatile("cp.async.commit_group;" ::: "memory")
#define CP_WAIT(n)  asm volatile("cp.async.wait_group %0;" :: "n"(n) : "memory")

__device__ __forceinline__ void mma_bf16(float* d, uint32_t a0, uint32_t a1,
                                         uint32_t a2, uint32_t a3,
                                         uint32_t b0, uint32_t b1) {
    asm volatile(
        "mma.sync.aligned.m16n8k16.row.col.f32.bf16.bf16.f32 "
        "{%0,%1,%2,%3}, {%4,%5,%6,%7}, {%8,%9}, {%0,%1,%2,%3};"
        : "+f"(d[0]), "+f"(d[1]), "+f"(d[2]), "+f"(d[3])
        : "r"(a0), "r"(a1), "r"(a2), "r"(a3), "r"(b0), "r"(b1));
}
__device__ __forceinline__ void ldsm_x2_trans(uint32_t& r0, uint32_t& r1, uint32_t addr) {
    asm volatile("ldmatrix.sync.aligned.m8n8.x2.trans.shared.b16 {%0,%1}, [%2];"
                 : "=r"(r0), "=r"(r1) : "r"(addr));
}
// pack (lo, hi) fp32 -> bf16x2  (cvt d, a, b: a->upper)
__device__ __forceinline__ uint32_t pack_bf16x2(float lo, float hi) {
    uint32_t d;
    asm("cvt.rn.bf16x2.f32 %0, %1, %2;" : "=r"(d) : "f"(hi), "f"(lo));
    return d;
}

// ---------------- conversion kernels ----------------
__global__ void convert_hilo(const float4* __restrict__ x,
                             uint2* __restrict__ hi, uint2* __restrict__ lo, int n4) {
    int i = blockIdx.x * 256 + threadIdx.x;
    if (i >= n4) return;
    float4 v = x[i];
    bf16 h0 = __float2bfloat16(v.x), h1 = __float2bfloat16(v.y);
    bf16 h2 = __float2bfloat16(v.z), h3 = __float2bfloat16(v.w);
    bf16 l0 = __float2bfloat16(v.x - __bfloat162float(h0));
    bf16 l1 = __float2bfloat16(v.y - __bfloat162float(h1));
    bf16 l2 = __float2bfloat16(v.z - __bfloat162float(h2));
    bf16 l3 = __float2bfloat16(v.w - __bfloat162float(h3));
    union U { bf16 b[4]; uint2 u; } uh, ul;
    uh.b[0] = h0; uh.b[1] = h1; uh.b[2] = h2; uh.b[3] = h3;
    ul.b[0] = l0; ul.b[1] = l1; ul.b[2] = l2; ul.b[3] = l3;
    hi[i] = uh.u;
    lo[i] = ul.u;
}

__global__ void wtrans_hilo(const float* __restrict__ W,
                            bf16* __restrict__ Th, bf16* __restrict__ Tl) {
    __shared__ float t[32][33];
    int tx = threadIdx.x, ty = threadIdx.y;
    int col  = blockIdx.x * 32 + tx;
    int row0 = blockIdx.y * 32;
    for (int j = ty; j < 32; j += 8)
        t[j][tx] = W[(size_t)(row0 + j) * DM + col];
    __syncthreads();
    int ocol  = row0 + tx;
    int orow0 = blockIdx.x * 32;
    for (int j = ty; j < 32; j += 8) {
        float v = t[tx][j];
        bf16 h = __float2bfloat16(v);
        bf16 l = __float2bfloat16(v - __bfloat162float(h));
        Th[(size_t)(orow0 + j) * DM + ocol] = h;
        Tl[(size_t)(orow0 + j) * DM + ocol] = l;
    }
}

// ---------------- HMMA bf16x3 GEMM (SPLIT: write bf16 hi/lo; else fp32) ----------------
#define GBK 32
#define MAT_ELEMS (128 * GBK)
#define STAGE_ELEMS (4 * MAT_ELEMS)
#define GEMM_SMEM_BYTES (2 * STAGE_ELEMS * 2)

__device__ __forceinline__ int swz(int row, int k) {
    int quad = (k >> 3) ^ (row & 3) ^ ((row >> 2) & 1);
    return row * GBK + quad * 8 + (k & 7);
}

template<bool SPLIT>
__global__ __launch_bounds__(256, 2)
void gemm_bf16x3(const bf16* __restrict__ Ahi, const bf16* __restrict__ Alo,
                 const bf16* __restrict__ Bhi, const bf16* __restrict__ Blo,
                 float* __restrict__ C, bf16* __restrict__ Ch, bf16* __restrict__ Cl,
                 int M, int N, int K) {
    extern __shared__ bf16 sm[];
    const int tid = threadIdx.x;
    const int wid = tid >> 5;
    const int lane = tid & 31;
    const int rowC = blockIdx.y * 128;
    const int colC = blockIdx.x * 128;

    const int wm = (wid >> 2) * 64;
    const int wn = (wid & 3) * 32;
    const int r  = lane >> 2;
    const int cq = (lane & 3) * 2;

    float acc[4][4][4];
#pragma unroll
    for (int i = 0; i < 4; i++)
#pragma unroll
        for (int j = 0; j < 4; j++)
#pragma unroll
            for (int t = 0; t < 4; t++) acc[i][j][t] = 0.f;

    auto load_stage = [&](int s, int c) {
        const size_t k0 = (size_t)c * GBK;
        bf16* st = sm + s * STAGE_ELEMS;
#pragma unroll
        for (int t = 0; t < 2; t++) {
            int idx = tid + t * 256;
            int row = idx >> 2;
            int q   = idx & 3;
            uint32_t dsto = smem_u32(st) + swz(row, q * 8) * 2;
            const bf16* ga = Ahi + (size_t)(rowC + row) * K + k0 + q * 8;
            const bf16* gl = Alo + (size_t)(rowC + row) * K + k0 + q * 8;
            const bf16* gb = Bhi + (size_t)(colC + row) * K + k0 + q * 8;
            const bf16* gc = Blo + (size_t)(colC + row) * K + k0 + q * 8;
            CP_ASYNC16(dsto,                 ga);
            CP_ASYNC16(dsto + MAT_ELEMS * 2, gl);
            CP_ASYNC16(dsto + MAT_ELEMS * 4, gb);
            CP_ASYNC16(dsto + MAT_ELEMS * 6, gc);
        }
    };

    const int nchunk = K / GBK;
    load_stage(0, 0);
    CP_COMMIT();

    for (int c = 0; c < nchunk; c++) {
        const int s = c & 1;
        if (c + 1 < nchunk) {
            load_stage(s ^ 1, c + 1);
            CP_COMMIT();
            CP_WAIT(1);
        } else {
            CP_WAIT(0);
        }
        __syncthreads();

        const bf16* Ah_s = sm + s * STAGE_ELEMS;
        const bf16* Al_s = Ah_s + MAT_ELEMS;
        const bf16* Bh_s = Ah_s + 2 * MAT_ELEMS;
        const bf16* Bl_s = Ah_s + 3 * MAT_ELEMS;

#pragma unroll
        for (int kk = 0; kk < GBK; kk += 16) {
            uint32_t ra[4][4], rb[4][2];
#pragma unroll
            for (int i = 0; i < 4; i++) {
                int m = wm + i * 16;
                ra[i][0] = *(const uint32_t*)(Ah_s + swz(m + r,     kk + cq));
                ra[i][1] = *(const uint32_t*)(Ah_s + swz(m + r + 8, kk + cq));
                ra[i][2] = *(const uint32_t*)(Ah_s + swz(m + r,     kk + cq + 8));
                ra[i][3] = *(const uint32_t*)(Ah_s + swz(m + r + 8, kk + cq + 8));
            }
#pragma unroll
            for (int j = 0; j < 4; j++) {
                int n = wn + j * 8 + r;
                rb[j][0] = *(const uint32_t*)(Bh_s + swz(n, kk + cq));
                rb[j][1] = *(const uint32_t*)(Bh_s + swz(n, kk + cq + 8));
            }
#pragma unroll
            for (int i = 0; i < 4; i++)
#pragma unroll
                for (int j = 0; j < 4; j++)
                    mma_bf16(acc[i][j], ra[i][0], ra[i][1], ra[i][2], ra[i][3],
                             rb[j][0], rb[j][1]);
#pragma unroll
            for (int j = 0; j < 4; j++) {
                int n = wn + j * 8 + r;
                rb[j][0] = *(const uint32_t*)(Bl_s + swz(n, kk + cq));
                rb[j][1] = *(const uint32_t*)(Bl_s + swz(n, kk + cq + 8));
            }
#pragma unroll
            for (int i = 0; i < 4; i++)
#pragma unroll
                for (int j = 0; j < 4; j++)
                    mma_bf16(acc[i][j], ra[i][0], ra[i][1], ra[i][2], ra[i][3],
                             rb[j][0], rb[j][1]);
#pragma unroll
            for (int i = 0; i < 4; i++) {
                int m = wm + i * 16;
                ra[i][0] = *(const uint32_t*)(Al_s + swz(m + r,     kk + cq));
                ra[i][1] = *(const uint32_t*)(Al_s + swz(m + r + 8, kk + cq));
                ra[i][2] = *(const uint32_t*)(Al_s + swz(m + r,     kk + cq + 8));
                ra[i][3] = *(const uint32_t*)(Al_s + swz(m + r + 8, kk + cq + 8));
            }
#pragma unroll
            for (int j = 0; j < 4; j++) {
                int n = wn + j * 8 + r;
                rb[j][0] = *(const uint32_t*)(Bh_s + swz(n, kk + cq));
                rb[j][1] = *(const uint32_t*)(Bh_s + swz(n, kk + cq + 8));
            }
#pragma unroll
            for (int i = 0; i < 4; i++)
#pragma unroll
                for (int j = 0; j < 4; j++)
                    mma_bf16(acc[i][j], ra[i][0], ra[i][1], ra[i][2], ra[i][3],
                             rb[j][0], rb[j][1]);
        }
        __syncthreads();
    }

#pragma unroll
    for (int i = 0; i < 4; i++) {
        int row0 = rowC + wm + i * 16 + r;
#pragma unroll
        for (int j = 0; j < 4; j++) {
            int col = colC + wn + j * 8 + cq;
            if (SPLIT) {
#pragma unroll
                for (int p = 0; p < 2; p++) {
                    float x0 = acc[i][j][p * 2 + 0], x1 = acc[i][j][p * 2 + 1];
                    bf16 h0 = __float2bfloat16(x0), h1 = __float2bfloat16(x1);
                    uint32_t ph = ((uint32_t)__bfloat16_as_ushort(h1) << 16)
                                |  (uint32_t)__bfloat16_as_ushort(h0);
                    uint32_t pl = pack_bf16x2(x0 - __bfloat162float(h0),
                                              x1 - __bfloat162float(h1));
                    size_t off = (size_t)(row0 + p * 8) * N + col;
                    *(uint32_t*)(Ch + off) = ph;
                    *(uint32_t*)(Cl + off) = pl;
                }
            } else {
                *(float2*)(C + (size_t)row0 * N + col) =
                    make_float2(acc[i][j][0], acc[i][j][1]);
                *(float2*)(C + (size_t)(row0 + 8) * N + col) =
                    make_float2(acc[i][j][2], acc[i][j][3]);
            }
        }
    }
}

// ---------------- HMMA flash attention (causal, bf16x3) ----------------
// grid (SEQ/64, BATCH*NH), 128 threads (4 warps, each 16 query rows).
#define AST  72                           // smem row stride (bf16)
#define AMAT (64 * AST)                   // 4608 elems / matrix
#define ATT_SMEM_BYTES (10 * AMAT * 2)    // Qh,Ql + 2 stages x (Kh,Kl,Vh,Vl)

__global__ __launch_bounds__(128, 2)
void attn_hmma(const bf16* __restrict__ Qh_g, const bf16* __restrict__ Ql_g,
               const bf16* __restrict__ Kh_g, const bf16* __restrict__ Kl_g,
               const bf16* __restrict__ Vh_g, const bf16* __restrict__ Vl_g,
               bf16* __restrict__ Ah_g, bf16* __restrict__ Al_g) {
    extern __shared__ bf16 sm[];
    const int bh = blockIdx.y;
    const int b  = bh >> 4;
    const int h  = bh & 15;
    const int m0 = blockIdx.x * 64;

    const int tid  = threadIdx.x;
    const int wid  = tid >> 5;
    const int lane = tid & 31;
    const int r    = lane >> 2;
    const int cq   = (lane & 3) * 2;
    const int wm   = wid * 16;

    const size_t rowbase = (size_t)b * SEQ;
    const int    colb    = h * DK;

    const uint32_t smb = smem_u32(sm);

    // ---- Q tile load (hi/lo), scale 0.125 applied later via exact bf16 scaling:
    // 0.125 is a power of two -> scale q fragments after load (multiply bf16x2).
    // Simpler: scale fp32 scores instead (exact): fold 0.125 into softmax input.
    {
        for (int i = tid; i < 512; i += 128) {
            int row = i >> 3, q = i & 7;
            uint32_t dst = smb + (uint32_t)(row * AST + q * 8) * 2;
            size_t g = (rowbase + m0 + row) * (size_t)DM + colb + q * 8;
            CP_ASYNC16(dst,            Qh_g + g);
            CP_ASYNC16(dst + AMAT * 2, Ql_g + g);
        }
    }
    auto load_kv = [&](int s, int n0) {
        uint32_t bbase = smb + (uint32_t)(2 + s * 4) * AMAT * 2;
        for (int i = tid; i < 512; i += 128) {
            int row = i >> 3, q = i & 7;
            uint32_t dst = bbase + (uint32_t)(row * AST + q * 8) * 2;
            size_t g = (rowbase + n0 + row) * (size_t)DM + colb + q * 8;
            CP_ASYNC16(dst,            Kh_g + g);
            CP_ASYNC16(dst + AMAT * 2, Kl_g + g);
            CP_ASYNC16(dst + AMAT * 4, Vh_g + g);
            CP_ASYNC16(dst + AMAT * 6, Vl_g + g);
        }
    };

    load_kv(0, 0);
    CP_COMMIT();

    const int T = m0 / 64 + 1;
    float m_i[2] = {-INFINITY, -INFINITY};
    float l_i[2] = {0.f, 0.f};
    float O[8][4];
#pragma unroll
    for (int j = 0; j < 8; j++)
#pragma unroll
        for (int t = 0; t < 4; t++) O[j][t] = 0.f;

    uint32_t qh[4][4], ql[4][4];

    for (int t = 0; t < T; t++) {
        if (t + 1 < T) {
            load_kv((t + 1) & 1, (t + 1) * 64);
            CP_COMMIT();
            CP_WAIT(1);
        } else {
            CP_WAIT(0);
        }
        __syncthreads();

        if (t == 0) {
            const bf16* Qs = sm;
            const bf16* Qls = sm + AMAT;
#pragma unroll
            for (int kc = 0; kc < 4; kc++) {
                qh[kc][0] = *(const uint32_t*)(Qs  + (wm + r)     * AST + kc * 16 + cq);
                qh[kc][1] = *(const uint32_t*)(Qs  + (wm + r + 8) * AST + kc * 16 + cq);
                qh[kc][2] = *(const uint32_t*)(Qs  + (wm + r)     * AST + kc * 16 + cq + 8);
                qh[kc][3] = *(const uint32_t*)(Qs  + (wm + r + 8) * AST + kc * 16 + cq + 8);
                ql[kc][0] = *(const uint32_t*)(Qls + (wm + r)     * AST + kc * 16 + cq);
                ql[kc][1] = *(const uint32_t*)(Qls + (wm + r + 8) * AST + kc * 16 + cq);
                ql[kc][2] = *(const uint32_t*)(Qls + (wm + r)     * AST + kc * 16 + cq + 8);
                ql[kc][3] = *(const uint32_t*)(Qls + (wm + r + 8) * AST + kc * 16 + cq + 8);
            }
        }

        const bf16* Ks  = sm + (2 + (t & 1) * 4) * AMAT;
        const bf16* Kls = Ks + AMAT;
        const uint32_t vbase  = smb + (uint32_t)(2 + (t & 1) * 4 + 2) * AMAT * 2;

        float sacc[8][4];
#pragma unroll
        for (int j = 0; j < 8; j++)
#pragma unroll
            for (int c = 0; c < 4; c++) sacc[j][c] = 0.f;

#pragma unroll
        for (int kc = 0; kc < 4; kc++) {
#pragma unroll
            for (int j = 0; j < 8; j++) {
                const int n = j * 8 + r;
                uint32_t kh0 = *(const uint32_t*)(Ks  + n * AST + kc * 16 + cq);
                uint32_t kh1 = *(const uint32_t*)(Ks  + n * AST + kc * 16 + cq + 8);
                uint32_t kl0 = *(const uint32_t*)(Kls + n * AST + kc * 16 + cq);
                uint32_t kl1 = *(const uint32_t*)(Kls + n * AST + kc * 16 + cq + 8);
                mma_bf16(sacc[j], qh[kc][0], qh[kc][1], qh[kc][2], qh[kc][3], kh0, kh1);
                mma_bf16(sacc[j], qh[kc][0], qh[kc][1], qh[kc][2], qh[kc][3], kl0, kl1);
                mma_bf16(sacc[j], ql[kc][0], ql[kc][1], ql[kc][2], ql[kc][3], kh0, kh1);
            }
        }

        // scale by 1/sqrt(dk) and causal mask on diagonal tile
#pragma unroll
        for (int j = 0; j < 8; j++)
#pragma unroll
            for (int c = 0; c < 4; c++) sacc[j][c] *= 0.125f;

        if (t == T - 1) {
            const int qr0 = m0 + wm + r;
#pragma unroll
            for (int j = 0; j < 8; j++) {
                const int key0 = t * 64 + j * 8 + cq;
                if (key0 + 0 > qr0)     sacc[j][0] = -INFINITY;
                if (key0 + 1 > qr0)     sacc[j][1] = -INFINITY;
                if (key0 + 0 > qr0 + 8) sacc[j][2] = -INFINITY;
                if (key0 + 1 > qr0 + 8) sacc[j][3] = -INFINITY;
            }
        }

        // online softmax
        float mx0 = -INFINITY, mx1 = -INFINITY;
#pragma unroll
        for (int j = 0; j < 8; j++) {
            mx0 = fmaxf(mx0, fmaxf(sacc[j][0], sacc[j][1]));
            mx1 = fmaxf(mx1, fmaxf(sacc[j][2], sacc[j][3]));
        }
        mx0 = fmaxf(mx0, __shfl_xor_sync(0xffffffffu, mx0, 1));
        mx0 = fmaxf(mx0, __shfl_xor_sync(0xffffffffu, mx0, 2));
        mx1 = fmaxf(mx1, __shfl_xor_sync(0xffffffffu, mx1, 1));
        mx1 = fmaxf(mx1, __shfl_xor_sync(0xffffffffu, mx1, 2));
        const float mn0 = fmaxf(m_i[0], mx0);
        const float mn1 = fmaxf(m_i[1], mx1);
        const float a0 = __expf(m_i[0] - mn0);
        const float a1 = __expf(m_i[1] - mn1);
        float s0 = 0.f, s1 = 0.f;
#pragma unroll
        for (int j = 0; j < 8; j++) {
            sacc[j][0] = __expf(sacc[j][0] - mn0); s0 += sacc[j][0];
            sacc[j][1] = __expf(sacc[j][1] - mn0); s0 += sacc[j][1];
            sacc[j][2] = __expf(sacc[j][2] - mn1); s1 += sacc[j][2];
            sacc[j][3] = __expf(sacc[j][3] - mn1); s1 += sacc[j][3];
        }
        s0 += __shfl_xor_sync(0xffffffffu, s0, 1);
        s0 += __shfl_xor_sync(0xffffffffu, s0, 2);
        s1 += __shfl_xor_sync(0xffffffffu, s1, 1);
        s1 += __shfl_xor_sync(0xffffffffu, s1, 2);
        l_i[0] = l_i[0] * a0 + s0;
        l_i[1] = l_i[1] * a1 + s1;
        m_i[0] = mn0; m_i[1] = mn1;
#pragma unroll
        for (int j = 0; j < 8; j++) {
            O[j][0] *= a0; O[j][1] *= a0;
            O[j][2] *= a1; O[j][3] *= a1;
        }

        // PV: P fragments from registers (hi + residual lo), V via ldmatrix.trans
#pragma unroll
        for (int kc = 0; kc < 4; kc++) {
            uint32_t ph[4], pl[4];
#pragma unroll
            for (int half = 0; half < 2; half++) {
                const int jj = kc * 2 + half;
                float x0 = sacc[jj][0], x1 = sacc[jj][1];
                float x2 = sacc[jj][2], x3 = sacc[jj][3];
                bf16 h0 = __float2bfloat16(x0), h1 = __float2bfloat16(x1);
                bf16 h2 = __float2bfloat16(x2), h3 = __float2bfloat16(x3);
                ph[half * 2 + 0] = ((uint32_t)__bfloat16_as_ushort(h1) << 16)
                                 |  (uint32_t)__bfloat16_as_ushort(h0);
                ph[half * 2 + 1] = ((uint32_t)__bfloat16_as_ushort(h3) << 16)
                                 |  (uint32_t)__bfloat16_as_ushort(h2);
                pl[half * 2 + 0] = pack_bf16x2(x0 - __bfloat162float(h0),
                                               x1 - __bfloat162float(h1));
                pl[half * 2 + 1] = pack_bf16x2(x2 - __bfloat162float(h2),
                                               x3 - __bfloat162float(h3));
            }
            // wait: frag order must be a0=(r,klo),a1=(r+8,klo),a2=(r,khi),a3=(r+8,khi)
            // ph[0]=(r, k cq of jj=2kc)  ph[1]=(r+8, same)  ph[2]=(r, k+8) ph[3]=(r+8,k+8)  ✓
            const int lrow = kc * 16 + (lane & 7) + ((lane >> 3) & 1) * 8;
#pragma unroll
            for (int j = 0; j < 8; j++) {
                uint32_t addr = vbase + (uint32_t)(lrow * AST + j * 8) * 2;
                uint32_t vh0, vh1, vl0, vl1;
                ldsm_x2_trans(vh0, vh1, addr);
                ldsm_x2_trans(vl0, vl1, addr + AMAT * 2);
                mma_bf16(O[j], ph[0], ph[1], ph[2], ph[3], vh0, vh1);
                mma_bf16(O[j], ph[0], ph[1], ph[2], ph[3], vl0, vl1);
                mma_bf16(O[j], pl[0], pl[1], pl[2], pl[3], vh0, vh1);
            }
        }
        __syncthreads();
    }

    // epilogue: O /= l, split hi/lo, store
    const float inv0 = 1.f / l_i[0];
    const float inv1 = 1.f / l_i[1];
#pragma unroll
    for (int j = 0; j < 8; j++) {
        const int col = colb + j * 8 + cq;
        const size_t row0 = (rowbase + m0 + wm + r) * (size_t)DM + col;
        const size_t row8 = row0 + 8 * (size_t)DM;
        float x0 = O[j][0] * inv0, x1 = O[j][1] * inv0;
        float x2 = O[j][2] * inv1, x3 = O[j][3] * inv1;
        bf16 h0 = __float2bfloat16(x0), h1 = __float2bfloat16(x1);
        bf16 h2 = __float2bfloat16(x2), h3 = __float2bfloat16(x3);
        *(uint32_t*)(Ah_g + row0) = ((uint32_t)__bfloat16_as_ushort(h1) << 16)
                                  |  (uint32_t)__bfloat16_as_ushort(h0);
        *(uint32_t*)(Ah_g + row8) = ((uint32_t)__bfloat16_as_ushort(h3) << 16)
                                  |  (uint32_t)__bfloat16_as_ushort(h2);
        *(uint32_t*)(Al_g + row0) = pack_bf16x2(x0 - __bfloat162float(h0),
                                                x1 - __bfloat162float(h1));
        *(uint32_t*)(Al_g + row8) = pack_bf16x2(x2 - __bfloat162float(h2),
                                                x3 - __bfloat162float(h3));
    }
}

// ================= launch =================
extern "C" void kernel_launch(void* const* d_in, const int* in_sizes, int n_in,
                              void* d_out, int out_size) {
    (void)in_sizes; (void)n_in; (void)out_size;
    const float* X  = (const float*)d_in[0];
    const float* Wq = (const float*)d_in[1];
    const float* Wk = (const float*)d_in[2];
    const float* Wv = (const float*)d_in[3];
    const float* Wo = (const float*)d_in[4];

    bf16 *xhi, *xlo, *qh, *qlo, *kh, *kl, *vh, *vl, *ahi, *alo;
    cudaGetSymbolAddress((void**)&xhi, g_Xhi); cudaGetSymbolAddress((void**)&xlo, g_Xlo);
    cudaGetSymbolAddress((void**)&qh, g_Qh);   cudaGetSymbolAddress((void**)&qlo, g_Ql);
    cudaGetSymbolAddress((void**)&kh, g_Kh);   cudaGetSymbolAddress((void**)&kl, g_Kl);
    cudaGetSymbolAddress((void**)&vh, g_Vh);   cudaGetSymbolAddress((void**)&vl, g_Vl);
    cudaGetSymbolAddress((void**)&ahi, g_Ahi); cudaGetSymbolAddress((void**)&alo, g_Alo);

    bf16 *wqh, *wql, *wkh, *wkl, *wvh, *wvl, *woh, *wol;
    cudaGetSymbolAddress((void**)&wqh, g_Wqh); cudaGetSymbolAddress((void**)&wql, g_Wql);
    cudaGetSymbolAddress((void**)&wkh, g_Wkh); cudaGetSymbolAddress((void**)&wkl, g_Wkl);
    cudaGetSymbolAddress((void**)&wvh, g_Wvh); cudaGetSymbolAddress((void**)&wvl, g_Wvl);
    cudaGetSymbolAddress((void**)&woh, g_Woh); cudaGetSymbolAddress((void**)&wol, g_Wol);

    cudaFuncSetAttribute(gemm_bf16x3<true>,
                         cudaFuncAttributeMaxDynamicSharedMemorySize, GEMM_SMEM_BYTES);
    cudaFuncSetAttribute(gemm_bf16x3<false>,
                         cudaFuncAttributeMaxDynamicSharedMemorySize, GEMM_SMEM_BYTES);
    cudaFuncSetAttribute(attn_hmma,
                         cudaFuncAttributeMaxDynamicSharedMemorySize, ATT_SMEM_BYTES);

    {
        int n4 = MROWS * DM / 4;
        convert_hilo<<<(n4 + 255) / 256, 256>>>((const float4*)X, (uint2*)xhi, (uint2*)xlo, n4);
    }
    {
        dim3 g(DM / 32, DM / 32), bb(32, 8);
        wtrans_hilo<<<g, bb>>>(Wq, wqh, wql);
        wtrans_hilo<<<g, bb>>>(Wk, wkh, wkl);
        wtrans_hilo<<<g, bb>>>(Wv, wvh, wvl);
        wtrans_hilo<<<g, bb>>>(Wo, woh, wol);
    }

    dim3 gGemm(DM / 128, MROWS / 128);
    gemm_bf16x3<true><<<gGemm, 256, GEMM_SMEM_BYTES>>>(
        xhi, xlo, wqh, wql, nullptr, qh, qlo, MROWS, DM, DM);
    gemm_bf16x3<true><<<gGemm, 256, GEMM_SMEM_BYTES>>>(
        xhi, xlo, wkh, wkl, nullptr, kh, kl, MROWS, DM, DM);
    gemm_bf16x3<true><<<gGemm, 256, GEMM_SMEM_BYTES>>>(
        xhi, xlo, wvh, wvl, nullptr, vh, vl, MROWS, DM, DM);

    dim3 gAttn(SEQ / 64, BATCH * NH);
    attn_hmma<<<gAttn, 128, ATT_SMEM_BYTES>>>(qh, qlo, kh, kl, vh, vl, ahi, alo);

    gemm_bf16x3<false><<<gGemm, 256, GEMM_SMEM_BYTES>>>(
        ahi, alo, woh, wol, (float*)d_out, nullptr, nullptr, MROWS, DM, DM);
}

// round 5
// speedup vs baseline: 3.3549x; 1.1122x over previous
#include <cuda_runtime.h>
#include <cuda_bf16.h>
#include <cstdint>
#include <math.h>

#define BATCH 4
#define SEQ   2048
#define DM    1024
#define NH    16
#define DK    64
#define MROWS (BATCH * SEQ)   // 8192

typedef __nv_bfloat16 bf16;

// ---------------- scratch (allocation-free: __device__ globals) ----------------
__device__ bf16 g_Xhi[MROWS * DM], g_Xlo[MROWS * DM];
__device__ bf16 g_Qh[MROWS * DM], g_Ql[MROWS * DM];
__device__ bf16 g_Kh[MROWS * DM], g_Kl[MROWS * DM];
__device__ bf16 g_Vh[MROWS * DM], g_Vl[MROWS * DM];
__device__ bf16 g_Ahi[MROWS * DM], g_Alo[MROWS * DM];

__device__ bf16 g_Wqh[DM * DM], g_Wql[DM * DM];
__device__ bf16 g_Wkh[DM * DM], g_Wkl[DM * DM];
__device__ bf16 g_Wvh[DM * DM], g_Wvl[DM * DM];
__device__ bf16 g_Woh[DM * DM], g_Wol[DM * DM];

// ---------------- common helpers ----------------
__device__ __forceinline__ uint32_t smem_u32(const void* p) {
    uint32_t a;
    asm("{ .reg .u64 t; cvta.to.shared.u64 t, %1; cvt.u32.u64 %0, t; }"
        : "=r"(a) : "l"(p));
    return a;
}
#define CP_ASYNC16(dst, src) \
    asm volatile("cp.async.cg.shared.global [%0], [%1], 16;" :: "r"(dst), "l"(src))
#define CP_COMMIT() asm volatile("cp.async.commit_group;" ::: "memory")
#define CP_WAIT(n)  asm volatile("cp.async.wait_group %0;" :: "n"(n) : "memory")

__device__ __forceinline__ void mma_bf16(float* d, const uint32_t* a,
                                         uint32_t b0, uint32_t b1) {
    asm volatile(
        "mma.sync.aligned.m16n8k16.row.col.f32.bf16.bf16.f32 "
        "{%0,%1,%2,%3}, {%4,%5,%6,%7}, {%8,%9}, {%0,%1,%2,%3};"
        : "+f"(d[0]), "+f"(d[1]), "+f"(d[2]), "+f"(d[3])
        : "r"(a[0]), "r"(a[1]), "r"(a[2]), "r"(a[3]), "r"(b0), "r"(b1));
}
__device__ __forceinline__ void ldsm_x4(uint32_t& r0, uint32_t& r1,
                                        uint32_t& r2, uint32_t& r3, uint32_t addr) {
    asm volatile("ldmatrix.sync.aligned.m8n8.x4.shared.b16 {%0,%1,%2,%3}, [%4];"
                 : "=r"(r0), "=r"(r1), "=r"(r2), "=r"(r3) : "r"(addr));
}
__device__ __forceinline__ void ldsm_x4_trans(uint32_t& r0, uint32_t& r1,
                                              uint32_t& r2, uint32_t& r3, uint32_t addr) {
    asm volatile("ldmatrix.sync.aligned.m8n8.x4.trans.shared.b16 {%0,%1,%2,%3}, [%4];"
                 : "=r"(r0), "=r"(r1), "=r"(r2), "=r"(r3) : "r"(addr));
}
__device__ __forceinline__ uint32_t pack_bf16x2(float lo, float hi) {
    uint32_t d;
    asm("cvt.rn.bf16x2.f32 %0, %1, %2;" : "=r"(d) : "f"(hi), "f"(lo));
    return d;
}

// ---------------- conversion kernels ----------------
__global__ void convert_hilo(const float4* __restrict__ x,
                             uint2* __restrict__ hi, uint2* __restrict__ lo, int n4) {
    int i = blockIdx.x * 256 + threadIdx.x;
    if (i >= n4) return;
    float4 v = x[i];
    bf16 h0 = __float2bfloat16(v.x), h1 = __float2bfloat16(v.y);
    bf16 h2 = __float2bfloat16(v.z), h3 = __float2bfloat16(v.w);
    bf16 l0 = __float2bfloat16(v.x - __bfloat162float(h0));
    bf16 l1 = __float2bfloat16(v.y - __bfloat162float(h1));
    bf16 l2 = __float2bfloat16(v.z - __bfloat162float(h2));
    bf16 l3 = __float2bfloat16(v.w - __bfloat162float(h3));
    union U { bf16 b[4]; uint2 u; } uh, ul;
    uh.b[0] = h0; uh.b[1] = h1; uh.b[2] = h2; uh.b[3] = h3;
    ul.b[0] = l0; ul.b[1] = l1; ul.b[2] = l2; ul.b[3] = l3;
    hi[i] = uh.u;
    lo[i] = ul.u;
}

__global__ void wtrans_hilo(const float* __restrict__ W,
                            bf16* __restrict__ Th, bf16* __restrict__ Tl) {
    __shared__ float t[32][33];
    int tx = threadIdx.x, ty = threadIdx.y;
    int col  = blockIdx.x * 32 + tx;
    int row0 = blockIdx.y * 32;
    for (int j = ty; j < 32; j += 8)
        t[j][tx] = W[(size_t)(row0 + j) * DM + col];
    __syncthreads();
    int ocol  = row0 + tx;
    int orow0 = blockIdx.x * 32;
    for (int j = ty; j < 32; j += 8) {
        float v = t[tx][j];
        bf16 h = __float2bfloat16(v);
        bf16 l = __float2bfloat16(v - __bfloat162float(h));
        Th[(size_t)(orow0 + j) * DM + ocol] = h;
        Tl[(size_t)(orow0 + j) * DM + ocol] = l;
    }
}

// ---------------- HMMA bf16x3 GEMM core ----------------
#define GBK 32
#define MAT_ELEMS (128 * GBK)
#define STAGE_ELEMS (4 * MAT_ELEMS)
#define GEMM_SMEM_BYTES (2 * STAGE_ELEMS * 2)

__device__ __forceinline__ int swz(int row, int k) {
    int quad = (k >> 3) ^ (row & 3) ^ ((row >> 2) & 1);
    return row * GBK + quad * 8 + (k & 7);
}

template<bool SPLIT>
__device__ __forceinline__
void gemm_core(const bf16* __restrict__ Ahi, const bf16* __restrict__ Alo,
               const bf16* __restrict__ Bhi, const bf16* __restrict__ Blo,
               float* __restrict__ C, bf16* __restrict__ Ch, bf16* __restrict__ Cl,
               int N, int K, bf16* sm) {
    const int tid = threadIdx.x;
    const int wid = tid >> 5;
    const int lane = tid & 31;
    const int rowC = blockIdx.y * 128;
    const int colC = blockIdx.x * 128;

    const int wm = (wid >> 2) * 64;
    const int wn = (wid & 3) * 32;
    const int r  = lane >> 2;
    const int cq = (lane & 3) * 2;

    float acc[4][4][4];
#pragma unroll
    for (int i = 0; i < 4; i++)
#pragma unroll
        for (int j = 0; j < 4; j++)
#pragma unroll
            for (int t = 0; t < 4; t++) acc[i][j][t] = 0.f;

    auto load_stage = [&](int s, int c) {
        const size_t k0 = (size_t)c * GBK;
        bf16* st = sm + s * STAGE_ELEMS;
#pragma unroll
        for (int t = 0; t < 2; t++) {
            int idx = tid + t * 256;
            int row = idx >> 2;
            int q   = idx & 3;
            uint32_t dsto = smem_u32(st) + swz(row, q * 8) * 2;
            const bf16* ga = Ahi + (size_t)(rowC + row) * K + k0 + q * 8;
            const bf16* gl = Alo + (size_t)(rowC + row) * K + k0 + q * 8;
            const bf16* gb = Bhi + (size_t)(colC + row) * K + k0 + q * 8;
            const bf16* gc = Blo + (size_t)(colC + row) * K + k0 + q * 8;
            CP_ASYNC16(dsto,                 ga);
            CP_ASYNC16(dsto + MAT_ELEMS * 2, gl);
            CP_ASYNC16(dsto + MAT_ELEMS * 4, gb);
            CP_ASYNC16(dsto + MAT_ELEMS * 6, gc);
        }
    };

    const int nchunk = K / GBK;
    load_stage(0, 0);
    CP_COMMIT();

    // ldmatrix address components
    const int a_r  = lane & 15;            // row within 16
    const int a_k  = (lane >> 4) * 8;      // k half
    const int b_j  = (lane >> 4) & 1;      // j within pair
    const int b_h  = (lane >> 3) & 1;      // k half
    const int b_r  = lane & 7;

    for (int c = 0; c < nchunk; c++) {
        const int s = c & 1;
        if (c + 1 < nchunk) {
            load_stage(s ^ 1, c + 1);
            CP_COMMIT();
            CP_WAIT(1);
        } else {
            CP_WAIT(0);
        }
        __syncthreads();

        const bf16* Ah_s = sm + s * STAGE_ELEMS;
        const bf16* Al_s = Ah_s + MAT_ELEMS;
        const bf16* Bh_s = Ah_s + 2 * MAT_ELEMS;
        const bf16* Bl_s = Ah_s + 3 * MAT_ELEMS;

#pragma unroll
        for (int kk = 0; kk < GBK; kk += 16) {
            uint32_t ah[4][4], bb[4][2];
            // ---- term 1: Ah x Bh ----
#pragma unroll
            for (int i = 0; i < 4; i++)
                ldsm_x4(ah[i][0], ah[i][1], ah[i][2], ah[i][3],
                        smem_u32(Ah_s + swz(wm + i * 16 + a_r, kk + a_k)));
#pragma unroll
            for (int jp = 0; jp < 2; jp++)
                ldsm_x4(bb[jp*2][0], bb[jp*2][1], bb[jp*2+1][0], bb[jp*2+1][1],
                        smem_u32(Bh_s + swz(wn + (jp*2 + b_j) * 8 + b_r, kk + b_h * 8)));
#pragma unroll
            for (int i = 0; i < 4; i++)
#pragma unroll
                for (int j = 0; j < 4; j++)
                    mma_bf16(acc[i][j], ah[i], bb[j][0], bb[j][1]);
            // ---- term 2: Ah x Bl ----
            uint32_t bl[4][2];
#pragma unroll
            for (int jp = 0; jp < 2; jp++)
                ldsm_x4(bl[jp*2][0], bl[jp*2][1], bl[jp*2+1][0], bl[jp*2+1][1],
                        smem_u32(Bl_s + swz(wn + (jp*2 + b_j) * 8 + b_r, kk + b_h * 8)));
#pragma unroll
            for (int i = 0; i < 4; i++)
#pragma unroll
                for (int j = 0; j < 4; j++)
                    mma_bf16(acc[i][j], ah[i], bl[j][0], bl[j][1]);
            // ---- term 3: Al x Bh ----
            uint32_t al[4][4];
#pragma unroll
            for (int i = 0; i < 4; i++)
                ldsm_x4(al[i][0], al[i][1], al[i][2], al[i][3],
                        smem_u32(Al_s + swz(wm + i * 16 + a_r, kk + a_k)));
#pragma unroll
            for (int i = 0; i < 4; i++)
#pragma unroll
                for (int j = 0; j < 4; j++)
                    mma_bf16(acc[i][j], al[i], bb[j][0], bb[j][1]);
        }
        __syncthreads();
    }

#pragma unroll
    for (int i = 0; i < 4; i++) {
        int row0 = rowC + wm + i * 16 + r;
#pragma unroll
        for (int j = 0; j < 4; j++) {
            int col = colC + wn + j * 8 + cq;
            if (SPLIT) {
#pragma unroll
                for (int p = 0; p < 2; p++) {
                    float x0 = acc[i][j][p * 2 + 0], x1 = acc[i][j][p * 2 + 1];
                    bf16 h0 = __float2bfloat16(x0), h1 = __float2bfloat16(x1);
                    uint32_t ph = ((uint32_t)__bfloat16_as_ushort(h1) << 16)
                                |  (uint32_t)__bfloat16_as_ushort(h0);
                    uint32_t pl = pack_bf16x2(x0 - __bfloat162float(h0),
                                              x1 - __bfloat162float(h1));
                    size_t off = (size_t)(row0 + p * 8) * N + col;
                    *(uint32_t*)(Ch + off) = ph;
                    *(uint32_t*)(Cl + off) = pl;
                }
            } else {
                *(float2*)(C + (size_t)row0 * N + col) =
                    make_float2(acc[i][j][0], acc[i][j][1]);
                *(float2*)(C + (size_t)(row0 + 8) * N + col) =
                    make_float2(acc[i][j][2], acc[i][j][3]);
            }
        }
    }
}

// fused QKV GEMM: grid (8, 64, 3)
__global__ __launch_bounds__(256, 2)
void gemm_qkv() {
    extern __shared__ bf16 sm[];
    if (blockIdx.z == 0)
        gemm_core<true>(g_Xhi, g_Xlo, g_Wqh, g_Wql, nullptr, g_Qh, g_Ql, DM, DM, sm);
    else if (blockIdx.z == 1)
        gemm_core<true>(g_Xhi, g_Xlo, g_Wkh, g_Wkl, nullptr, g_Kh, g_Kl, DM, DM, sm);
    else
        gemm_core<true>(g_Xhi, g_Xlo, g_Wvh, g_Wvl, nullptr, g_Vh, g_Vl, DM, DM, sm);
}

__global__ __launch_bounds__(256, 2)
void gemm_out(float* __restrict__ C) {
    extern __shared__ bf16 sm[];
    gemm_core<false>(g_Ahi, g_Alo, g_Woh, g_Wol, C, nullptr, nullptr, DM, DM, sm);
}

// ---------------- HMMA flash attention (causal, bf16x3) ----------------
#define AST  72
#define AMAT (64 * AST)
#define ATT_SMEM_BYTES (10 * AMAT * 2)

__global__ __launch_bounds__(128, 2)
void attn_hmma() {
    extern __shared__ bf16 sm[];
    const int bh = blockIdx.y;
    const int b  = bh >> 4;
    const int h  = bh & 15;
    // heavy (long-loop) blocks first to shrink the causal tail
    const int m0 = ((int)gridDim.x - 1 - (int)blockIdx.x) * 64;

    const int tid  = threadIdx.x;
    const int wid  = tid >> 5;
    const int lane = tid & 31;
    const int r    = lane >> 2;
    const int cq   = (lane & 3) * 2;
    const int wm   = wid * 16;

    const size_t rowbase = (size_t)b * SEQ;
    const int    colb    = h * DK;

    const uint32_t smb = smem_u32(sm);

    {
        for (int i = tid; i < 512; i += 128) {
            int row = i >> 3, q = i & 7;
            uint32_t dst = smb + (uint32_t)(row * AST + q * 8) * 2;
            size_t g = (rowbase + m0 + row) * (size_t)DM + colb + q * 8;
            CP_ASYNC16(dst,            g_Qh + g);
            CP_ASYNC16(dst + AMAT * 2, g_Ql + g);
        }
    }
    auto load_kv = [&](int s, int n0) {
        uint32_t bbase = smb + (uint32_t)(2 + s * 4) * AMAT * 2;
        for (int i = tid; i < 512; i += 128) {
            int row = i >> 3, q = i & 7;
            uint32_t dst = bbase + (uint32_t)(row * AST + q * 8) * 2;
            size_t g = (rowbase + n0 + row) * (size_t)DM + colb + q * 8;
            CP_ASYNC16(dst,            g_Kh + g);
            CP_ASYNC16(dst + AMAT * 2, g_Kl + g);
            CP_ASYNC16(dst + AMAT * 4, g_Vh + g);
            CP_ASYNC16(dst + AMAT * 6, g_Vl + g);
        }
    };

    load_kv(0, 0);
    CP_COMMIT();

    const int T = m0 / 64 + 1;
    float m_i[2] = {-INFINITY, -INFINITY};
    float l_i[2] = {0.f, 0.f};
    float O[8][4];
#pragma unroll
    for (int j = 0; j < 8; j++)
#pragma unroll
        for (int t = 0; t < 4; t++) O[j][t] = 0.f;

    uint32_t qh[4][4], ql[4][4];

    // ldmatrix address components
    const int a_r = lane & 15;
    const int a_k = (lane >> 4) * 8;
    const int b_j = (lane >> 4) & 1;
    const int b_h = (lane >> 3) & 1;
    const int b_r = lane & 7;

    for (int t = 0; t < T; t++) {
        if (t + 1 < T) {
            load_kv((t + 1) & 1, (t + 1) * 64);
            CP_COMMIT();
            CP_WAIT(1);
        } else {
            CP_WAIT(0);
        }
        __syncthreads();

        if (t == 0) {
#pragma unroll
            for (int kc = 0; kc < 4; kc++) {
                uint32_t ad = smb + (uint32_t)((wm + a_r) * AST + kc * 16 + a_k) * 2;
                ldsm_x4(qh[kc][0], qh[kc][1], qh[kc][2], qh[kc][3], ad);
                ldsm_x4(ql[kc][0], ql[kc][1], ql[kc][2], ql[kc][3], ad + AMAT * 2);
            }
        }

        const uint32_t kbase = smb + (uint32_t)(2 + (t & 1) * 4) * AMAT * 2;
        const uint32_t vbase = kbase + 2 * AMAT * 2;

        float sacc[8][4];
#pragma unroll
        for (int j = 0; j < 8; j++)
#pragma unroll
            for (int c = 0; c < 4; c++) sacc[j][c] = 0.f;

#pragma unroll
        for (int kc = 0; kc < 4; kc++) {
            uint32_t kh[8][2], kl[8][2];
#pragma unroll
            for (int jp = 0; jp < 4; jp++) {
                uint32_t ad = kbase
                    + (uint32_t)(((jp * 2 + b_j) * 8 + b_r) * AST + kc * 16 + b_h * 8) * 2;
                ldsm_x4(kh[jp*2][0], kh[jp*2][1], kh[jp*2+1][0], kh[jp*2+1][1], ad);
                ldsm_x4(kl[jp*2][0], kl[jp*2][1], kl[jp*2+1][0], kl[jp*2+1][1],
                        ad + AMAT * 2);
            }
#pragma unroll
            for (int j = 0; j < 8; j++) {
                mma_bf16(sacc[j], qh[kc], kh[j][0], kh[j][1]);
                mma_bf16(sacc[j], qh[kc], kl[j][0], kl[j][1]);
                mma_bf16(sacc[j], ql[kc], kh[j][0], kh[j][1]);
            }
        }

#pragma unroll
        for (int j = 0; j < 8; j++)
#pragma unroll
            for (int c = 0; c < 4; c++) sacc[j][c] *= 0.125f;

        if (t == T - 1) {
            const int qr0 = m0 + wm + r;
#pragma unroll
            for (int j = 0; j < 8; j++) {
                const int key0 = t * 64 + j * 8 + cq;
                if (key0 + 0 > qr0)     sacc[j][0] = -INFINITY;
                if (key0 + 1 > qr0)     sacc[j][1] = -INFINITY;
                if (key0 + 0 > qr0 + 8) sacc[j][2] = -INFINITY;
                if (key0 + 1 > qr0 + 8) sacc[j][3] = -INFINITY;
            }
        }

        float mx0 = -INFINITY, mx1 = -INFINITY;
#pragma unroll
        for (int j = 0; j < 8; j++) {
            mx0 = fmaxf(mx0, fmaxf(sacc[j][0], sacc[j][1]));
            mx1 = fmaxf(mx1, fmaxf(sacc[j][2], sacc[j][3]));
        }
        mx0 = fmaxf(mx0, __shfl_xor_sync(0xffffffffu, mx0, 1));
        mx0 = fmaxf(mx0, __shfl_xor_sync(0xffffffffu, mx0, 2));
        mx1 = fmaxf(mx1, __shfl_xor_sync(0xffffffffu, mx1, 1));
        mx1 = fmaxf(mx1, __shfl_xor_sync(0xffffffffu, mx1, 2));
        const float mn0 = fmaxf(m_i[0], mx0);
        const float mn1 = fmaxf(m_i[1], mx1);
        const float a0 = __expf(m_i[0] - mn0);
        const float a1 = __expf(m_i[1] - mn1);
        float s0 = 0.f, s1 = 0.f;
#pragma unroll
        for (int j = 0; j < 8; j++) {
            sacc[j][0] = __expf(sacc[j][0] - mn0); s0 += sacc[j][0];
            sacc[j][1] = __expf(sacc[j][1] - mn0); s0 += sacc[j][1];
            sacc[j][2] = __expf(sacc[j][2] - mn1); s1 += sacc[j][2];
            sacc[j][3] = __expf(sacc[j][3] - mn1); s1 += sacc[j][3];
        }
        s0 += __shfl_xor_sync(0xffffffffu, s0, 1);
        s0 += __shfl_xor_sync(0xffffffffu, s0, 2);
        s1 += __shfl_xor_sync(0xffffffffu, s1, 1);
        s1 += __shfl_xor_sync(0xffffffffu, s1, 2);
        l_i[0] = l_i[0] * a0 + s0;
        l_i[1] = l_i[1] * a1 + s1;
        m_i[0] = mn0; m_i[1] = mn1;
#pragma unroll
        for (int j = 0; j < 8; j++) {
            O[j][0] *= a0; O[j][1] *= a0;
            O[j][2] *= a1; O[j][3] *= a1;
        }

        // PV
#pragma unroll
        for (int kc = 0; kc < 4; kc++) {
            uint32_t ph[4], pl[4];
#pragma unroll
            for (int half = 0; half < 2; half++) {
                const int jj = kc * 2 + half;
                float x0 = sacc[jj][0], x1 = sacc[jj][1];
                float x2 = sacc[jj][2], x3 = sacc[jj][3];
                bf16 h0 = __float2bfloat16(x0), h1 = __float2bfloat16(x1);
                bf16 h2 = __float2bfloat16(x2), h3 = __float2bfloat16(x3);
                ph[half * 2 + 0] = ((uint32_t)__bfloat16_as_ushort(h1) << 16)
                                 |  (uint32_t)__bfloat16_as_ushort(h0);
                ph[half * 2 + 1] = ((uint32_t)__bfloat16_as_ushort(h3) << 16)
                                 |  (uint32_t)__bfloat16_as_ushort(h2);
                pl[half * 2 + 0] = pack_bf16x2(x0 - __bfloat162float(h0),
                                               x1 - __bfloat162float(h1));
                pl[half * 2 + 1] = pack_bf16x2(x2 - __bfloat162float(h2),
                                               x3 - __bfloat162float(h3));
            }
            const int lrow = kc * 16 + (lane & 7) + ((lane >> 3) & 1) * 8;
            const int lcolh = (lane >> 4);     // j within pair
#pragma unroll
            for (int jp = 0; jp < 4; jp++) {
                uint32_t addr = vbase
                    + (uint32_t)(lrow * AST + (jp * 2 + lcolh) * 8) * 2;
                uint32_t vh0, vh1, vh2, vh3, vl0, vl1, vl2, vl3;
                ldsm_x4_trans(vh0, vh1, vh2, vh3, addr);
                ldsm_x4_trans(vl0, vl1, vl2, vl3, addr + AMAT * 2);
                mma_bf16(O[jp * 2],     ph, vh0, vh1);
                mma_bf16(O[jp * 2],     ph, vl0, vl1);
                mma_bf16(O[jp * 2],     pl, vh0, vh1);
                mma_bf16(O[jp * 2 + 1], ph, vh2, vh3);
                mma_bf16(O[jp * 2 + 1], ph, vl2, vl3);
                mma_bf16(O[jp * 2 + 1], pl, vh2, vh3);
            }
        }
        __syncthreads();
    }

    const float inv0 = 1.f / l_i[0];
    const float inv1 = 1.f / l_i[1];
#pragma unroll
    for (int j = 0; j < 8; j++) {
        const int col = colb + j * 8 + cq;
        const size_t row0 = (rowbase + m0 + wm + r) * (size_t)DM + col;
        const size_t row8 = row0 + 8 * (size_t)DM;
        float x0 = O[j][0] * inv0, x1 = O[j][1] * inv0;
        float x2 = O[j][2] * inv1, x3 = O[j][3] * inv1;
        bf16 h0 = __float2bfloat16(x0), h1 = __float2bfloat16(x1);
        bf16 h2 = __float2bfloat16(x2), h3 = __float2bfloat16(x3);
        *(uint32_t*)(g_Ahi + row0) = ((uint32_t)__bfloat16_as_ushort(h1) << 16)
                                   |  (uint32_t)__bfloat16_as_ushort(h0);
        *(uint32_t*)(g_Ahi + row8) = ((uint32_t)__bfloat16_as_ushort(h3) << 16)
                                   |  (uint32_t)__bfloat16_as_ushort(h2);
        *(uint32_t*)(g_Alo + row0) = pack_bf16x2(x0 - __bfloat162float(h0),
                                                 x1 - __bfloat162float(h1));
        *(uint32_t*)(g_Alo + row8) = pack_bf16x2(x2 - __bfloat162float(h2),
                                                 x3 - __bfloat162float(h3));
    }
}

// ================= launch =================
extern "C" void kernel_launch(void* const* d_in, const int* in_sizes, int n_in,
                              void* d_out, int out_size) {
    (void)in_sizes; (void)n_in; (void)out_size;
    const float* X  = (const float*)d_in[0];
    const float* Wq = (const float*)d_in[1];
    const float* Wk = (const float*)d_in[2];
    const float* Wv = (const float*)d_in[3];
    const float* Wo = (const float*)d_in[4];

    bf16 *xhi, *xlo;
    cudaGetSymbolAddress((void**)&xhi, g_Xhi);
    cudaGetSymbolAddress((void**)&xlo, g_Xlo);
    bf16 *wqh, *wql, *wkh, *wkl, *wvh, *wvl, *woh, *wol;
    cudaGetSymbolAddress((void**)&wqh, g_Wqh); cudaGetSymbolAddress((void**)&wql, g_Wql);
    cudaGetSymbolAddress((void**)&wkh, g_Wkh); cudaGetSymbolAddress((void**)&wkl, g_Wkl);
    cudaGetSymbolAddress((void**)&wvh, g_Wvh); cudaGetSymbolAddress((void**)&wvl, g_Wvl);
    cudaGetSymbolAddress((void**)&woh, g_Woh); cudaGetSymbolAddress((void**)&wol, g_Wol);

    cudaFuncSetAttribute(gemm_qkv,
                         cudaFuncAttributeMaxDynamicSharedMemorySize, GEMM_SMEM_BYTES);
    cudaFuncSetAttribute(gemm_out,
                         cudaFuncAttributeMaxDynamicSharedMemorySize, GEMM_SMEM_BYTES);
    cudaFuncSetAttribute(attn_hmma,
                         cudaFuncAttributeMaxDynamicSharedMemorySize, ATT_SMEM_BYTES);

    {
        int n4 = MROWS * DM / 4;
        convert_hilo<<<(n4 + 255) / 256, 256>>>((const float4*)X, (uint2*)xhi, (uint2*)xlo, n4);
    }
    {
        dim3 g(DM / 32, DM / 32), bb(32, 8);
        wtrans_hilo<<<g, bb>>>(Wq, wqh, wql);
        wtrans_hilo<<<g, bb>>>(Wk, wkh, wkl);
        wtrans_hilo<<<g, bb>>>(Wv, wvh, wvl);
        wtrans_hilo<<<g, bb>>>(Wo, woh, wol);
    }

    gemm_qkv<<<dim3(DM / 128, MROWS / 128, 3), 256, GEMM_SMEM_BYTES>>>();

    dim3 gAttn(SEQ / 64, BATCH * NH);
    attn_hmma<<<gAttn, 128, ATT_SMEM_BYTES>>>();

    gemm_out<<<dim3(DM / 128, MROWS / 128), 256, GEMM_SMEM_BYTES>>>((float*)d_out);
}